// round 15
// baseline (speedup 1.0000x reference)
#include <cuda_runtime.h>
#include <cuda_fp16.h>
#include <math.h>
#include <float.h>
#include <stdint.h>

// ---------------- problem dims (fixed by setup_inputs) ----------------
#define D_MODEL 1024
#define N_HEADS 16
#define DH      64
#define D_FF    4096
#define NFAM    64
#define DICT    16384
#define BB      2
#define TT      2048
#define BT      (BB*TT)
#define TOPK    8
#define NCAND   16
#define EPS_F   1e-6f

#define X_N     ((size_t)BT * D_MODEL)
#define ATT_N   ((size_t)BB * N_HEADS * TT * TT)
#define FS_N    ((size_t)BT * NFAM)
#define X_OFF   ((size_t)0)
#define ATT_OFF (X_N)
#define FS_OFF  (X_N + ATT_N)
#define SC_OFF  (X_N + ATT_N + FS_N)

#define PD   ((size_t)BT * D_MODEL)
#define PW   ((size_t)D_MODEL * D_MODEL)
#define PF   ((size_t)D_FF * D_MODEL)
#define PH   ((size_t)BT * D_FF)
#define PE   ((size_t)DICT * D_MODEL)

// ---------------- fp32 scratch ----------------
__device__ float g_resid  [BT * D_MODEL];
__device__ float g_basis  [BT * D_MODEL];
__device__ float g_xrec   [BT * D_MODEL];
__device__ float g_x2     [BT * D_MODEL];
__device__ float g_up     [(size_t)BT * D_FF];
__device__ float g_rms1   [BT];
__device__ float g_rms2   [BT];
__device__ float g_spars  [BT];

// ---------------- fp16 planes ----------------
__device__ __align__(16) __half b_coeffs [(size_t)BT * DICT];   // 128 MB
__device__ __align__(16) __half b_resid_h[PD];
__device__ __align__(16) __half b_enc_h  [PE];
__device__ __align__(16) __half b_normed [PD];
__device__ __align__(16) __half b_normed2[PD];
__device__ __align__(16) __half b_qkv    [3 * PD];   // q/k/v fp16 planes
__device__ __align__(16) __half b_kmod   [PD];       // [bh][t][64]
__device__ __align__(16) __half b_vt     [PD];       // [bh][64][t]
__device__ __align__(16) __half b_ctx    [PD];
__device__ __align__(16) __half b_h      [PH];
__device__ __align__(16) __half b_wqkv   [3 * PW];   // packed wq/wk/wv
__device__ __align__(16) __half b_wo     [PW];
__device__ __align__(16) __half b_gw     [PF];
__device__ __align__(16) __half b_uw     [PF];
__device__ __align__(16) __half b_dw     [PF];
__device__ __align__(16) __half b_attn   [ATT_N];

// ===================== helpers (baseline PTX, sm_80+) =========
__device__ __forceinline__ uint32_t smem_u32(const void* p) {
    uint32_t a;
    asm("{ .reg .u64 t; cvta.to.shared.u64 t, %1; cvt.u32.u64 %0, t; }" : "=r"(a) : "l"(p));
    return a;
}
__device__ __forceinline__ void ldsm_x4(uint32_t& r0, uint32_t& r1, uint32_t& r2,
                                        uint32_t& r3, uint32_t addr) {
    asm volatile("ldmatrix.sync.aligned.m8n8.x4.shared.b16 {%0,%1,%2,%3}, [%4];"
                 : "=r"(r0), "=r"(r1), "=r"(r2), "=r"(r3) : "r"(addr));
}
__device__ __forceinline__ void mma_f16(float* d, const uint32_t* a, uint32_t b0, uint32_t b1) {
    asm volatile("mma.sync.aligned.m16n8k16.row.col.f32.f16.f16.f32 "
                 "{%0,%1,%2,%3},{%4,%5,%6,%7},{%8,%9},{%0,%1,%2,%3};"
                 : "+f"(d[0]), "+f"(d[1]), "+f"(d[2]), "+f"(d[3])
                 : "r"(a[0]), "r"(a[1]), "r"(a[2]), "r"(a[3]), "r"(b0), "r"(b1));
}
__device__ __forceinline__ void cpa16(uint32_t dst, const void* src) {
    asm volatile("cp.async.cg.shared.global [%0], [%1], 16;" :: "r"(dst), "l"(src) : "memory");
}
__device__ __forceinline__ void cpa_commit() { asm volatile("cp.async.commit_group;" ::: "memory"); }
__device__ __forceinline__ void cpa_wait1()  { asm volatile("cp.async.wait_group 1;" ::: "memory"); }
__device__ __forceinline__ void cpa_wait0()  { asm volatile("cp.async.wait_group 0;" ::: "memory"); }

// =====================================================================
// fp16 mma GEMM: C[M,N] = alpha*(A @ B^T) (+res), row-major, single pass.
// Tile 128 x BN (BN in {64,128,256}), BK=64, 3-stage cp.async pipeline,
// 128-byte smem rows with (c16 ^= row&7) swizzle.
// BN=256: 1 CTA/SM, warp tile 64x64 (MF=4, NF=8) — higher arithmetic
// intensity: load-issue 75% of MMA time instead of 100%+.
// OUT=0: fp32 C (+res, *alpha).
// OUT=2: fp16 store to Cp (*alpha).
// OUT=3: fp16 store of sigmoid(acc)*silu(res) to Cp   (gate GEMM + activation).
// aHead/cHead: base = (z>>4)*TT*ld + (z&15)*DH (per-head slice of [token][1024]).
// =====================================================================
template<int BN, int OUT>
__global__ void __launch_bounds__(256, (BN == 256) ? 1 : 2)
mma_gemm(const __half* __restrict__ A, int lda, size_t aZ, int aHead,
         const __half* __restrict__ B, int ldb, size_t bZ,
         float* __restrict__ C, int ldc, size_t cZ, int cHead,
         __half* __restrict__ Cp,
         const float* __restrict__ res, int K, float alpha)
{
    constexpr int APL = 128 * 128;             // bytes, A tile (128 rows x 128B)
    constexpr int BPL = BN * 128;
    constexpr int STG = APL + BPL;
    constexpr int UNITS = 1024 + BN * 8;       // 16B units per chunk
    constexpr int MF = (BN == 64) ? 2 : 4;
    constexpr int NF = (BN == 256) ? 8 : 4;
    constexpr int NG = NF / 2;                 // B ldsm groups (16 rows each)

    extern __shared__ char sm[];
    const int tid = threadIdx.x, wid = tid >> 5, lane = tid & 31;
    const int bm = blockIdx.y * 128, bn = blockIdx.x * BN;
    const int z = blockIdx.z;
    const uint32_t smb = smem_u32(sm);

    const size_t abase = aHead ? ((size_t)(z >> 4) * TT * lda + (size_t)(z & 15) * DH)
                               : (size_t)z * aZ;
    const __half* Ab = A + abase + (size_t)bm * lda;
    const __half* Bb = B + (size_t)z * bZ + (size_t)bn * ldb;

    const int wr = (BN == 64) ? (wid >> 1) : (wid >> 2);
    const int wc = (BN == 64) ? (wid & 1)  : (wid & 3);
    const int mrow0 = wr * (MF * 16);
    const int ncol0 = wc * (NF * 8);

    float acc[MF][NF][4];
#pragma unroll
    for (int m = 0; m < MF; m++)
#pragma unroll
        for (int n = 0; n < NF; n++)
#pragma unroll
            for (int q = 0; q < 4; q++) acc[m][n][q] = 0.f;

    const int NC = K >> 6;

    auto issue = [&](int c, int stage) {
        const int k0 = c << 6;
        const uint32_t sb = smb + stage * STG;
#pragma unroll
        for (int u = 0; u < UNITS / 256; u++) {
            const int idx = u * 256 + tid;
            if (idx < 1024) {
                const int r = idx >> 3, c8 = idx & 7;
                const uint32_t off = (uint32_t)(r * 128 + ((c8 ^ (r & 7)) << 4));
                cpa16(sb + off, Ab + (size_t)r * lda + k0 + c8 * 8);
            } else {
                const int j = idx - 1024;
                const int r = j >> 3, c8 = j & 7;
                const uint32_t off = (uint32_t)(r * 128 + ((c8 ^ (r & 7)) << 4));
                cpa16(sb + APL + off, Bb + (size_t)r * ldb + k0 + c8 * 8);
            }
        }
        cpa_commit();
    };

    issue(0, 0);
    if (NC > 1) issue(1, 1);

    for (int c = 0; c < NC; ++c) {
        if (c < NC - 1) cpa_wait1(); else cpa_wait0();
        __syncthreads();
        if (c + 2 < NC) issue(c + 2, (c + 2) % 3);

        const uint32_t aB = smb + (c % 3) * STG;
        const uint32_t bB = aB + APL;
#pragma unroll
        for (int ks = 0; ks < 4; ks++) {
            uint32_t af[MF][4];
#pragma unroll
            for (int m = 0; m < MF; m++) {
                const int row = mrow0 + m * 16 + (lane & 15);
                const int c16 = ks * 2 + (lane >> 4);
                ldsm_x4(af[m][0], af[m][1], af[m][2], af[m][3],
                        aB + row * 128 + ((c16 ^ (row & 7)) << 4));
            }
            uint32_t bf[NG][4];
#pragma unroll
            for (int g = 0; g < NG; g++) {
                const int row = ncol0 + g * 16 + (lane & 15);
                const int c16 = ks * 2 + (lane >> 4);
                ldsm_x4(bf[g][0], bf[g][1], bf[g][2], bf[g][3],
                        bB + row * 128 + ((c16 ^ (row & 7)) << 4));
            }
#pragma unroll
            for (int m = 0; m < MF; m++)
#pragma unroll
                for (int nf = 0; nf < NF; nf++)
                    mma_f16(acc[m][nf], af[m], bf[nf >> 1][nf & 1], bf[nf >> 1][(nf & 1) + 2]);
        }
    }

    // ---- epilogue ----
    const size_t cbase = cHead ? ((size_t)(z >> 4) * TT * ldc + (size_t)(z & 15) * DH)
                               : (size_t)z * cZ;
    if (OUT == 0) {
        float* Cb = C + cbase + (size_t)bm * ldc + bn;
        const float* Rb = res ? res + cbase + (size_t)bm * ldc + bn : (const float*)0;
#pragma unroll
        for (int m = 0; m < MF; m++) {
            const int r0 = mrow0 + m * 16 + (lane >> 2);
#pragma unroll
            for (int h = 0; h < 2; h++) {
                const int r = r0 + h * 8;
                float* crow = Cb + (size_t)r * ldc;
                const float* rrow = Rb ? Rb + (size_t)r * ldc : (const float*)0;
#pragma unroll
                for (int nf = 0; nf < NF; nf++) {
                    const int col = ncol0 + nf * 8 + (lane & 3) * 2;
                    float2 v;
                    v.x = acc[m][nf][2*h + 0] * alpha;
                    v.y = acc[m][nf][2*h + 1] * alpha;
                    if (rrow) { v.x += rrow[col]; v.y += rrow[col + 1]; }
                    *(float2*)(crow + col) = v;
                }
            }
        }
    } else if (OUT == 2) {
        __half* Ch = Cp + cbase + (size_t)bm * ldc + bn;
#pragma unroll
        for (int m = 0; m < MF; m++) {
            const int r0 = mrow0 + m * 16 + (lane >> 2);
#pragma unroll
            for (int h = 0; h < 2; h++) {
                const int r = r0 + h * 8;
#pragma unroll
                for (int nf = 0; nf < NF; nf++) {
                    const int col = ncol0 + nf * 8 + (lane & 3) * 2;
                    __half2 hh;
                    hh.x = __float2half_rn(acc[m][nf][2*h + 0] * alpha);
                    hh.y = __float2half_rn(acc[m][nf][2*h + 1] * alpha);
                    *(__half2*)(Ch + (size_t)r * ldc + col) = hh;
                }
            }
        }
    } else {   // OUT == 3: h = sigmoid(acc) * silu(res)   (acc=gate, res=up)
        __half* Ch = Cp + cbase + (size_t)bm * ldc + bn;
        const float* Ub = res + cbase + (size_t)bm * ldc + bn;
#pragma unroll
        for (int m = 0; m < MF; m++) {
            const int r0 = mrow0 + m * 16 + (lane >> 2);
#pragma unroll
            for (int h = 0; h < 2; h++) {
                const int r = r0 + h * 8;
                const float* urow = Ub + (size_t)r * ldc;
#pragma unroll
                for (int nf = 0; nf < NF; nf++) {
                    const int col = ncol0 + nf * 8 + (lane & 3) * 2;
                    __half2 hh;
#pragma unroll
                    for (int q = 0; q < 2; q++) {
                        const float g = acc[m][nf][2*h + q];
                        const float u = urow[col + q];
                        const float sg = 1.f / (1.f + __expf(-g));
                        const float su = u / (1.f + __expf(-u));
                        ((__half*)&hh)[q] = __float2half_rn(sg * su);
                    }
                    *(__half2*)(Ch + (size_t)r * ldc + col) = hh;
                }
            }
        }
    }
}

// =====================================================================
// fp32 -> fp16 convert kernel
// =====================================================================
__global__ void __launch_bounds__(256)
half_kernel(const float* __restrict__ s, __half* __restrict__ hi, size_t n2)
{
    const float2* s2 = (const float2*)s;
    __half2* h2 = (__half2*)hi;
    for (size_t i = (size_t)blockIdx.x * 256 + threadIdx.x; i < n2; i += (size_t)gridDim.x * 256) {
        const float2 v = s2[i];
        __half2 h;
        h.x = __float2half_rn(v.x); h.y = __float2half_rn(v.y);
        h2[i] = h;
    }
}

// =====================================================================
// Family basis pool -> scores, basis, resid fp32 + resid fp16 plane
// =====================================================================
__global__ void __launch_bounds__(256)
family_kernel(const float* __restrict__ x, const float* __restrict__ fgw,
              const float* __restrict__ proto, float* __restrict__ fs_out)
{
    __shared__ float xs[D_MODEL];
    __shared__ float sc[NFAM];
    const int row = blockIdx.x;
    const int tid = threadIdx.x;
    const float* xr = x + (size_t)row * D_MODEL;
    for (int d = tid; d < D_MODEL; d += 256) xs[d] = xr[d];
    __syncthreads();

    const int warp = tid >> 5, lane = tid & 31;
    for (int f = warp; f < NFAM; f += 8) {
        const float* w = fgw + (size_t)f * D_MODEL;
        float s = 0.f;
        for (int d = lane; d < D_MODEL; d += 32) s += xs[d] * w[d];
#pragma unroll
        for (int o = 16; o; o >>= 1) s += __shfl_xor_sync(0xffffffffu, s, o);
        if (lane == 0) sc[f] = s;
    }
    __syncthreads();

    if (tid < 32) {
        float m = fmaxf(sc[tid], sc[tid + 32]);
#pragma unroll
        for (int o = 16; o; o >>= 1) m = fmaxf(m, __shfl_xor_sync(0xffffffffu, m, o));
        const float e0 = __expf(sc[tid] - m);
        const float e1 = __expf(sc[tid + 32] - m);
        float s = e0 + e1;
#pragma unroll
        for (int o = 16; o; o >>= 1) s += __shfl_xor_sync(0xffffffffu, s, o);
        const float inv = 1.f / s;
        sc[tid]      = e0 * inv;
        sc[tid + 32] = e1 * inv;
    }
    __syncthreads();

    if (tid < NFAM) fs_out[(size_t)row * NFAM + tid] = sc[tid];

    for (int d = tid; d < D_MODEL; d += 256) {
        float b = 0.f;
#pragma unroll 8
        for (int f = 0; f < NFAM; f++) b += sc[f] * proto[f * D_MODEL + d];
        const size_t idx = (size_t)row * D_MODEL + d;
        g_basis[idx] = b;
        const float r = xs[d] - b;
        g_resid[idx] = r;
        b_resid_h[idx] = __float2half_rn(r);
    }
}

// =====================================================================
// Top-16 candidates from approx fp16 coeffs, exact fp32 re-rank to top-8.
// =====================================================================
__global__ void __launch_bounds__(256)
topk_kernel(const float* __restrict__ dict_w, const float* __restrict__ enc_w,
            const float* __restrict__ bias)
{
    __shared__ float sval[256 * NCAND];
    __shared__ int   sidx[256 * NCAND];
    __shared__ float rv[256];
    __shared__ int   ri[256];
    __shared__ int   rp[256];
    __shared__ int   candi[NCAND];
    __shared__ float exv[NCAND];
    __shared__ float selv[TOPK];
    __shared__ int   seli[TOPK];

    const int row = blockIdx.x;
    const int tid = threadIdx.x;
    const __half* cr = b_coeffs + (size_t)row * DICT;

    float lv[NCAND]; int li[NCAND];
#pragma unroll
    for (int r = 0; r < NCAND; r++) { lv[r] = -FLT_MAX; li[r] = 0x7fffffff; }
    for (int j = tid; j < DICT; j += 256) {
        const float v = __half2float(cr[j]);
        if (v > lv[NCAND-1]) {
            int p = NCAND - 1;
            while (p > 0 && lv[p-1] < v) { lv[p] = lv[p-1]; li[p] = li[p-1]; p--; }
            lv[p] = v; li[p] = j;
        }
    }
#pragma unroll
    for (int r = 0; r < NCAND; r++) { sval[tid*NCAND + r] = lv[r]; sidx[tid*NCAND + r] = li[r]; }
    __syncthreads();

    for (int sel = 0; sel < NCAND; sel++) {
        float bv = -FLT_MAX; int bi = 0x7fffffff; int bp = 0;
#pragma unroll
        for (int r = 0; r < NCAND; r++) {
            const int p = tid*NCAND + r;
            const float v = sval[p]; const int ix = sidx[p];
            if (v > bv || (v == bv && ix < bi)) { bv = v; bi = ix; bp = p; }
        }
        rv[tid] = bv; ri[tid] = bi; rp[tid] = bp;
        __syncthreads();
        for (int s = 128; s > 0; s >>= 1) {
            if (tid < s) {
                if (rv[tid+s] > rv[tid] || (rv[tid+s] == rv[tid] && ri[tid+s] < ri[tid])) {
                    rv[tid] = rv[tid+s]; ri[tid] = ri[tid+s]; rp[tid] = rp[tid+s];
                }
            }
            __syncthreads();
        }
        if (tid == 0) {
            candi[sel] = ri[0];
            sval[rp[0]] = -FLT_MAX; sidx[rp[0]] = 0x7fffffff;
        }
        __syncthreads();
    }

    {
        const int warp = tid >> 5, lane = tid & 31;
        const float* rr = g_resid + (size_t)row * D_MODEL;
        for (int j = warp; j < NCAND; j += 8) {
            const float* er = enc_w + (size_t)candi[j] * D_MODEL;
            float s = 0.f;
            for (int d = lane; d < D_MODEL; d += 32) s += rr[d] * er[d];
#pragma unroll
            for (int o = 16; o; o >>= 1) s += __shfl_xor_sync(0xffffffffu, s, o);
            if (lane == 0) exv[j] = s;
        }
    }
    __syncthreads();

    if (tid == 0) {
        unsigned used = 0;
        float ssum = 0.f;
        for (int sel = 0; sel < TOPK; sel++) {
            float bv = -FLT_MAX; int bi = 0x7fffffff; int bp = -1;
            for (int j = 0; j < NCAND; j++) {
                if (used & (1u << j)) continue;
                const float v = exv[j]; const int ix = candi[j];
                if (v > bv || (v == bv && ix < bi)) { bv = v; bi = ix; bp = j; }
            }
            used |= (1u << bp);
            selv[sel] = bv; seli[sel] = bi;
            ssum += fabsf(bv);
        }
        g_spars[row] = ssum;
    }
    __syncthreads();

    for (int d = tid; d < D_MODEL; d += 256) {
        float o = g_basis[(size_t)row * D_MODEL + d] + bias[d];
#pragma unroll
        for (int j = 0; j < TOPK; j++) o += selv[j] * dict_w[(size_t)seli[j] * D_MODEL + d];
        g_xrec[(size_t)row * D_MODEL + d] = o;
    }
}

// =====================================================================
// RMSNorm -> fp16 plane
// =====================================================================
__global__ void __launch_bounds__(256)
rmsnorm_kernel(const float* __restrict__ in, const float* __restrict__ w,
               __half* __restrict__ hi, float* __restrict__ rmsbuf)
{
    __shared__ float red[256];
    const int row = blockIdx.x, tid = threadIdx.x;
    const float* xr = in + (size_t)row * D_MODEL;
    float s = 0.f;
    for (int d = tid; d < D_MODEL; d += 256) { const float v = xr[d]; s += v * v; }
    red[tid] = s;
    __syncthreads();
    for (int st = 128; st > 0; st >>= 1) { if (tid < st) red[tid] += red[tid + st]; __syncthreads(); }
    const float rms = sqrtf(red[0] / (float)D_MODEL + EPS_F);
    const float inv = 1.f / rms;
    for (int d = tid; d < D_MODEL; d += 256)
        hi[(size_t)row * D_MODEL + d] = __float2half_rn(w[d] * xr[d] * inv);
    if (tid == 0) rmsbuf[row] = rms;
}

// =====================================================================
// k_mod -> fp16 plane  [bh][t][64]   (reads fp16 k plane)
// =====================================================================
__global__ void __launch_bounds__(256)
kmod_kernel(const __half* __restrict__ kbuf, const float* __restrict__ rel)
{
    __shared__ float ks[64][65];
    __shared__ float ts[64][65];
    const int bh = blockIdx.y, b = bh >> 4, h = bh & 15;
    const int t0 = blockIdx.x * 64;
    const int tid = threadIdx.x;
    for (int i = tid; i < 4096; i += 256) {
        const int r = i >> 6, c = i & 63;
        ks[r][c] = __half2float(kbuf[(size_t)(b*TT + t0 + r) * D_MODEL + h*DH + c]);
        ts[r][c] = rel[(size_t)h*DH*DH + r*DH + c];
    }
    __syncthreads();
    const int tx = tid & 15, ty = tid >> 4;
    float acc[4][4] = {};
#pragma unroll
    for (int d = 0; d < 64; d++) {
        float ra[4], rb[4];
#pragma unroll
        for (int i = 0; i < 4; i++) ra[i] = ks[ty*4 + i][d];
#pragma unroll
        for (int j = 0; j < 4; j++) rb[j] = ts[d][tx*4 + j];
#pragma unroll
        for (int i = 0; i < 4; i++)
#pragma unroll
            for (int j = 0; j < 4; j++) acc[i][j] += ra[i] * rb[j];
    }
#pragma unroll
    for (int i = 0; i < 4; i++)
#pragma unroll
        for (int j = 0; j < 4; j++)
            b_kmod[((size_t)bh*TT + t0 + ty*4 + i) * DH + tx*4 + j] = __float2half_rn(acc[i][j]);
}

// =====================================================================
// V transpose -> fp16 plane  [bh][64][t]   (reads fp16 v plane)
// =====================================================================
__global__ void __launch_bounds__(256)
vtrans_kernel(const __half* __restrict__ v)
{
    __shared__ __half t[64][72];
    const int z = blockIdx.y, b = z >> 4, h = z & 15;
    const int t0 = blockIdx.x * 64;
    for (int i = threadIdx.x; i < 4096; i += 256) {
        const int r = i >> 6, c = i & 63;
        t[r][c] = v[(size_t)(b*TT + t0 + r) * D_MODEL + h*DH + c];
    }
    __syncthreads();
    for (int i = threadIdx.x; i < 4096; i += 256) {
        const int e = i >> 6, r = i & 63;
        b_vt[(size_t)z * DH * TT + (size_t)e * TT + t0 + r] = t[r][e];
    }
}

// =====================================================================
// Row softmax over 2048, fp32 in place + fp16 plane copy
// =====================================================================
__global__ void __launch_bounds__(256)
softmax_kernel(float* __restrict__ P, __half* __restrict__ ph)
{
    __shared__ float red[256];
    const size_t row = blockIdx.x;
    float* p = P + row * (size_t)TT;
    __half* oh = ph + row * (size_t)TT;
    const int tid = threadIdx.x;
    float v[8];
#pragma unroll
    for (int i = 0; i < 8; i++) v[i] = p[tid + i*256];
    float m = v[0];
#pragma unroll
    for (int i = 1; i < 8; i++) m = fmaxf(m, v[i]);
    red[tid] = m;
    __syncthreads();
    for (int st = 128; st > 0; st >>= 1) { if (tid < st) red[tid] = fmaxf(red[tid], red[tid+st]); __syncthreads(); }
    m = red[0];
    __syncthreads();
    float s = 0.f;
#pragma unroll
    for (int i = 0; i < 8; i++) { v[i] = __expf(v[i] - m); s += v[i]; }
    red[tid] = s;
    __syncthreads();
    for (int st = 128; st > 0; st >>= 1) { if (tid < st) red[tid] += red[tid+st]; __syncthreads(); }
    const float inv = 1.f / red[0];
#pragma unroll
    for (int i = 0; i < 8; i++) {
        const float vv = v[i] * inv;
        p[tid + i*256] = vv;
        oh[tid + i*256] = __float2half_rn(vv);
    }
}

// =====================================================================
// Final scalars
// =====================================================================
__global__ void __launch_bounds__(256)
finalize_kernel(float* __restrict__ out)
{
    __shared__ float s1[256], s2[256], s3[256];
    const int tid = threadIdx.x;
    float a = 0.f, b = 0.f, c = 0.f;
    for (int i = tid; i < BT; i += 256) { a += g_spars[i]; b += g_rms1[i]; c += g_rms2[i]; }
    s1[tid] = a; s2[tid] = b; s3[tid] = c;
    __syncthreads();
    for (int st = 128; st > 0; st >>= 1) {
        if (tid < st) { s1[tid] += s1[tid+st]; s2[tid] += s2[tid+st]; s3[tid] += s3[tid+st]; }
        __syncthreads();
    }
    if (tid == 0) {
        out[SC_OFF + 0] = s1[0] / ((float)BB * (float)TT * (float)DICT);
        out[SC_OFF + 1] = s2[0] / (float)BT;
        out[SC_OFF + 2] = s3[0] / (float)BT;
    }
}

// =====================================================================
// host launcher
// =====================================================================
extern "C" void kernel_launch(void* const* d_in, const int* in_sizes, int n_in,
                              void* d_out, int out_size)
{
    (void)in_sizes; (void)n_in; (void)out_size;
    const float* x     = (const float*)d_in[0];
    const float* proto = (const float*)d_in[2];
    const float* fgw   = (const float*)d_in[3];
    const float* dictw = (const float*)d_in[4];
    const float* encw  = (const float*)d_in[5];
    const float* wq    = (const float*)d_in[6];
    const float* wk    = (const float*)d_in[7];
    const float* wv    = (const float*)d_in[8];
    const float* wo    = (const float*)d_in[9];
    const float* rel   = (const float*)d_in[10];
    const float* gatew = (const float*)d_in[11];
    const float* upw   = (const float*)d_in[12];
    const float* downw = (const float*)d_in[13];
    const float* n1w   = (const float*)d_in[14];
    const float* n2w   = (const float*)d_in[15];
    const float* bias  = (const float*)d_in[16];
    float* out = (float*)d_out;

    const int SM_256 = 3 * (16384 + 32768);   // 147456
    const int SM_64  = 3 * (16384 +  8192);   // 73728
    cudaFuncSetAttribute(mma_gemm<256,0>, cudaFuncAttributeMaxDynamicSharedMemorySize, SM_256);
    cudaFuncSetAttribute(mma_gemm<256,2>, cudaFuncAttributeMaxDynamicSharedMemorySize, SM_256);
    cudaFuncSetAttribute(mma_gemm<256,3>, cudaFuncAttributeMaxDynamicSharedMemorySize, SM_256);
    cudaFuncSetAttribute(mma_gemm<64,2>,  cudaFuncAttributeMaxDynamicSharedMemorySize, SM_64);

    float *p_xrec, *p_x2, *p_up, *p_rms1, *p_rms2;
    cudaGetSymbolAddress((void**)&p_xrec, g_xrec);
    cudaGetSymbolAddress((void**)&p_x2,   g_x2);
    cudaGetSymbolAddress((void**)&p_up,   g_up);
    cudaGetSymbolAddress((void**)&p_rms1, g_rms1);
    cudaGetSymbolAddress((void**)&p_rms2, g_rms2);

    __half *pb_coeffs, *pb_resid, *pb_enc, *pb_normed, *pb_normed2, *pb_qkv, *pb_kmod,
           *pb_vt, *pb_ctx, *pb_h, *pb_attn, *pb_wqkv, *pb_wo, *pb_gw, *pb_uw, *pb_dw;
    cudaGetSymbolAddress((void**)&pb_coeffs,  b_coeffs);
    cudaGetSymbolAddress((void**)&pb_resid,   b_resid_h);
    cudaGetSymbolAddress((void**)&pb_enc,     b_enc_h);
    cudaGetSymbolAddress((void**)&pb_normed,  b_normed);
    cudaGetSymbolAddress((void**)&pb_normed2, b_normed2);
    cudaGetSymbolAddress((void**)&pb_qkv,     b_qkv);
    cudaGetSymbolAddress((void**)&pb_kmod,    b_kmod);
    cudaGetSymbolAddress((void**)&pb_vt,      b_vt);
    cudaGetSymbolAddress((void**)&pb_ctx,     b_ctx);
    cudaGetSymbolAddress((void**)&pb_h,       b_h);
    cudaGetSymbolAddress((void**)&pb_attn,    b_attn);
    cudaGetSymbolAddress((void**)&pb_wqkv,    b_wqkv);
    cudaGetSymbolAddress((void**)&pb_wo,      b_wo);
    cudaGetSymbolAddress((void**)&pb_gw,      b_gw);
    cudaGetSymbolAddress((void**)&pb_uw,      b_uw);
    cudaGetSymbolAddress((void**)&pb_dw,      b_dw);

    // weight converts
    half_kernel<<<1024, 256>>>(encw, pb_enc, PE/2);
    half_kernel<<<256, 256>>>(wq, pb_wqkv,          PW/2);
    half_kernel<<<256, 256>>>(wk, pb_wqkv + PW,     PW/2);
    half_kernel<<<256, 256>>>(wv, pb_wqkv + 2*PW,   PW/2);
    family_kernel<<<BT, 256>>>(x, fgw, proto, out + FS_OFF);

    // approx coeffs (fp16 out; exact re-rank in topk)
    mma_gemm<256,2><<<dim3(DICT/256, BT/128, 1), 256, SM_256>>>(
        pb_resid, D_MODEL, 0, 0, pb_enc, D_MODEL, 0,
        nullptr, DICT, 0, 0, pb_coeffs, nullptr, D_MODEL, 1.0f);

    // remaining weight converts (overlap with coeffs GEMM tail)
    half_kernel<<<256, 256>>>(wo,    pb_wo, PW/2);
    half_kernel<<<512, 256>>>(gatew, pb_gw, PF/2);
    half_kernel<<<512, 256>>>(upw,   pb_uw, PF/2);
    half_kernel<<<512, 256>>>(downw, pb_dw, PF/2);

    // top-16 + exact fp32 re-rank -> x_rec, sparsity
    topk_kernel<<<BT, 256>>>(dictw, encw, bias);

    // norm1 -> fp16 plane
    rmsnorm_kernel<<<BT, 256>>>(p_xrec, n1w, pb_normed, p_rms1);

    // q,k,v in ONE batched launch (fp16 planes out)
    mma_gemm<256,2><<<dim3(D_MODEL/256, BT/128, 3), 256, SM_256>>>(
        pb_normed, D_MODEL, 0, 0, pb_wqkv, D_MODEL, PW,
        nullptr, D_MODEL, PD, 0, pb_qkv, nullptr, D_MODEL, 1.0f);

    // k_mod + V transpose (fp16 in/out)
    kmod_kernel<<<dim3(TT/64, BB*N_HEADS), 256>>>(pb_qkv + PD, rel);
    vtrans_kernel<<<dim3(TT/64, BB*N_HEADS), 256>>>(pb_qkv + 2*PD);

    // logits -> d_out fp32, softmax -> fp32 + fp16 plane
    mma_gemm<256,0><<<dim3(TT/256, TT/128, BB*N_HEADS), 256, SM_256>>>(
        pb_qkv, D_MODEL, 0, 1, pb_kmod, DH, (size_t)TT*DH,
        out + ATT_OFF, TT, (size_t)TT*TT, 0, nullptr, nullptr, DH, 0.125f);
    softmax_kernel<<<BB*N_HEADS*TT, 256>>>(out + ATT_OFF, pb_attn);

    // ctx = attn @ v (fp16 out, head-sliced)
    mma_gemm<64,2><<<dim3(1, TT/128, BB*N_HEADS), 256, SM_64>>>(
        pb_attn, TT, (size_t)TT*TT, 0, pb_vt, TT, (size_t)DH*TT,
        nullptr, D_MODEL, 0, 1, pb_ctx, nullptr, TT, 1.0f);

    // x2 = x + ctx @ wo^T
    mma_gemm<256,0><<<dim3(D_MODEL/256, BT/128, 1), 256, SM_256>>>(
        pb_ctx, D_MODEL, 0, 0, pb_wo, D_MODEL, 0,
        p_x2, D_MODEL, 0, 0, nullptr, x, D_MODEL, 1.0f);

    // norm2 -> fp16 plane
    rmsnorm_kernel<<<BT, 256>>>(p_x2, n2w, pb_normed2, p_rms2);

    // FFN: up (fp32), gate (+fused activation -> b_h fp16)
    mma_gemm<256,0><<<dim3(D_FF/256, BT/128, 1), 256, SM_256>>>(
        pb_normed2, D_MODEL, 0, 0, pb_uw, D_MODEL, 0,
        p_up, D_FF, 0, 0, nullptr, nullptr, D_MODEL, 1.0f);
    mma_gemm<256,3><<<dim3(D_FF/256, BT/128, 1), 256, SM_256>>>(
        pb_normed2, D_MODEL, 0, 0, pb_gw, D_MODEL, 0,
        nullptr, D_FF, 0, 0, pb_h, p_up, D_MODEL, 1.0f);

    // final x = x2 + h @ down^T -> d_out
    mma_gemm<256,0><<<dim3(D_MODEL/256, BT/128, 1), 256, SM_256>>>(
        pb_h, D_FF, 0, 0, pb_dw, D_FF, 0,
        out + X_OFF, D_MODEL, 0, 0, nullptr, p_x2, D_FF, 1.0f);

    // scalars
    finalize_kernel<<<1, 256>>>(out);
}

// round 16
// speedup vs baseline: 1.4916x; 1.4916x over previous
#include <cuda_runtime.h>
#include <cuda_fp16.h>
#include <math.h>
#include <float.h>
#include <stdint.h>

// ---------------- problem dims (fixed by setup_inputs) ----------------
#define D_MODEL 1024
#define N_HEADS 16
#define DH      64
#define D_FF    4096
#define NFAM    64
#define DICT    16384
#define BB      2
#define TT      2048
#define BT      (BB*TT)
#define TOPK    8
#define NCAND   16
#define EPS_F   1e-6f

#define X_N     ((size_t)BT * D_MODEL)
#define ATT_N   ((size_t)BB * N_HEADS * TT * TT)
#define FS_N    ((size_t)BT * NFAM)
#define X_OFF   ((size_t)0)
#define ATT_OFF (X_N)
#define FS_OFF  (X_N + ATT_N)
#define SC_OFF  (X_N + ATT_N + FS_N)

#define PD   ((size_t)BT * D_MODEL)
#define PW   ((size_t)D_MODEL * D_MODEL)
#define PF   ((size_t)D_FF * D_MODEL)
#define PH   ((size_t)BT * D_FF)
#define PE   ((size_t)DICT * D_MODEL)

// ---------------- fp32 scratch ----------------
__device__ float g_resid  [BT * D_MODEL];
__device__ float g_basis  [BT * D_MODEL];
__device__ float g_xrec   [BT * D_MODEL];
__device__ float g_x2     [BT * D_MODEL];
__device__ float g_up     [(size_t)BT * D_FF];
__device__ float g_rms1   [BT];
__device__ float g_rms2   [BT];
__device__ float g_spars  [BT];

// ---------------- fp16 planes ----------------
__device__ __align__(16) __half b_coeffs [(size_t)BT * DICT];   // 128 MB
__device__ __align__(16) __half b_resid_h[PD];
__device__ __align__(16) __half b_enc_h  [PE];
__device__ __align__(16) __half b_normed [PD];
__device__ __align__(16) __half b_normed2[PD];
__device__ __align__(16) __half b_qkv    [3 * PD];   // q/k/v fp16 planes
__device__ __align__(16) __half b_kmod   [PD];       // [bh][t][64]
__device__ __align__(16) __half b_vt     [PD];       // [bh][64][t]
__device__ __align__(16) __half b_ctx    [PD];
__device__ __align__(16) __half b_h      [PH];
__device__ __align__(16) __half b_wqkv   [3 * PW];   // packed wq/wk/wv
__device__ __align__(16) __half b_wo     [PW];
__device__ __align__(16) __half b_gw     [PF];
__device__ __align__(16) __half b_uw     [PF];
__device__ __align__(16) __half b_dw     [PF];
__device__ __align__(16) __half b_attn   [ATT_N];    // fp16 logits, then probs

// ===================== helpers (baseline PTX, sm_80+) =========
__device__ __forceinline__ uint32_t smem_u32(const void* p) {
    uint32_t a;
    asm("{ .reg .u64 t; cvta.to.shared.u64 t, %1; cvt.u32.u64 %0, t; }" : "=r"(a) : "l"(p));
    return a;
}
__device__ __forceinline__ void ldsm_x4(uint32_t& r0, uint32_t& r1, uint32_t& r2,
                                        uint32_t& r3, uint32_t addr) {
    asm volatile("ldmatrix.sync.aligned.m8n8.x4.shared.b16 {%0,%1,%2,%3}, [%4];"
                 : "=r"(r0), "=r"(r1), "=r"(r2), "=r"(r3) : "r"(addr));
}
__device__ __forceinline__ void mma_f16(float* d, const uint32_t* a, uint32_t b0, uint32_t b1) {
    asm volatile("mma.sync.aligned.m16n8k16.row.col.f32.f16.f16.f32 "
                 "{%0,%1,%2,%3},{%4,%5,%6,%7},{%8,%9},{%0,%1,%2,%3};"
                 : "+f"(d[0]), "+f"(d[1]), "+f"(d[2]), "+f"(d[3])
                 : "r"(a[0]), "r"(a[1]), "r"(a[2]), "r"(a[3]), "r"(b0), "r"(b1));
}
__device__ __forceinline__ void cpa16(uint32_t dst, const void* src) {
    asm volatile("cp.async.cg.shared.global [%0], [%1], 16;" :: "r"(dst), "l"(src) : "memory");
}
__device__ __forceinline__ void cpa_commit() { asm volatile("cp.async.commit_group;" ::: "memory"); }
__device__ __forceinline__ void cpa_wait1()  { asm volatile("cp.async.wait_group 1;" ::: "memory"); }
__device__ __forceinline__ void cpa_wait0()  { asm volatile("cp.async.wait_group 0;" ::: "memory"); }

// =====================================================================
// fp16 mma GEMM: C[M,N] = alpha*(A @ B^T) (+res), row-major, single pass.
// Tile 128 x BN (BN in {64,128}), BK=64, 3-stage cp.async pipeline,
// 128-byte smem rows with (c16 ^= row&7) swizzle.  (BN=256 falsified in R15:
// 128 acc regs/thread -> spills; BN=128/MF=4/NF=4 is the register sweet spot.)
// OUT=0: fp32 C (+res, *alpha).
// OUT=2: fp16 store to Cp (*alpha).
// OUT=3: fp16 store of sigmoid(acc)*silu(res) to Cp   (gate GEMM + activation).
// aHead/cHead: base = (z>>4)*TT*ld + (z&15)*DH (per-head slice of [token][1024]).
// =====================================================================
template<int BN, int OUT>
__global__ void __launch_bounds__(256, 2)
mma_gemm(const __half* __restrict__ A, int lda, size_t aZ, int aHead,
         const __half* __restrict__ B, int ldb, size_t bZ,
         float* __restrict__ C, int ldc, size_t cZ, int cHead,
         __half* __restrict__ Cp,
         const float* __restrict__ res, int K, float alpha)
{
    constexpr int APL = 128 * 128;             // bytes, A tile (128 rows x 128B)
    constexpr int BPL = BN * 128;
    constexpr int STG = APL + BPL;
    constexpr int UNITS = 1024 + BN * 8;       // 16B units per chunk
    constexpr int MF = (BN == 128) ? 4 : 2;
    constexpr int NF = 4;

    extern __shared__ char sm[];
    const int tid = threadIdx.x, wid = tid >> 5, lane = tid & 31;
    const int bm = blockIdx.y * 128, bn = blockIdx.x * BN;
    const int z = blockIdx.z;
    const uint32_t smb = smem_u32(sm);

    const size_t abase = aHead ? ((size_t)(z >> 4) * TT * lda + (size_t)(z & 15) * DH)
                               : (size_t)z * aZ;
    const __half* Ab = A + abase + (size_t)bm * lda;
    const __half* Bb = B + (size_t)z * bZ + (size_t)bn * ldb;

    const int wr = (BN == 128) ? (wid >> 2) : (wid >> 1);
    const int wc = (BN == 128) ? (wid & 3)  : (wid & 1);
    const int mrow0 = wr * (MF * 16);
    const int ncol0 = wc * 32;

    float acc[MF][NF][4];
#pragma unroll
    for (int m = 0; m < MF; m++)
#pragma unroll
        for (int n = 0; n < NF; n++)
#pragma unroll
            for (int q = 0; q < 4; q++) acc[m][n][q] = 0.f;

    const int NC = K >> 6;

    auto issue = [&](int c, int stage) {
        const int k0 = c << 6;
        const uint32_t sb = smb + stage * STG;
#pragma unroll
        for (int u = 0; u < UNITS / 256; u++) {
            const int idx = u * 256 + tid;
            if (idx < 1024) {
                const int r = idx >> 3, c8 = idx & 7;
                const uint32_t off = (uint32_t)(r * 128 + ((c8 ^ (r & 7)) << 4));
                cpa16(sb + off, Ab + (size_t)r * lda + k0 + c8 * 8);
            } else {
                const int j = idx - 1024;
                const int r = j >> 3, c8 = j & 7;
                const uint32_t off = (uint32_t)(r * 128 + ((c8 ^ (r & 7)) << 4));
                cpa16(sb + APL + off, Bb + (size_t)r * ldb + k0 + c8 * 8);
            }
        }
        cpa_commit();
    };

    issue(0, 0);
    if (NC > 1) issue(1, 1);

    for (int c = 0; c < NC; ++c) {
        if (c < NC - 1) cpa_wait1(); else cpa_wait0();
        __syncthreads();
        if (c + 2 < NC) issue(c + 2, (c + 2) % 3);

        const uint32_t aB = smb + (c % 3) * STG;
        const uint32_t bB = aB + APL;
#pragma unroll
        for (int ks = 0; ks < 4; ks++) {
            uint32_t af[MF][4];
#pragma unroll
            for (int m = 0; m < MF; m++) {
                const int row = mrow0 + m * 16 + (lane & 15);
                const int c16 = ks * 2 + (lane >> 4);
                ldsm_x4(af[m][0], af[m][1], af[m][2], af[m][3],
                        aB + row * 128 + ((c16 ^ (row & 7)) << 4));
            }
            uint32_t bf[2][4];
#pragma unroll
            for (int g = 0; g < 2; g++) {
                const int row = ncol0 + g * 16 + (lane & 15);
                const int c16 = ks * 2 + (lane >> 4);
                ldsm_x4(bf[g][0], bf[g][1], bf[g][2], bf[g][3],
                        bB + row * 128 + ((c16 ^ (row & 7)) << 4));
            }
#pragma unroll
            for (int m = 0; m < MF; m++)
#pragma unroll
                for (int nf = 0; nf < NF; nf++)
                    mma_f16(acc[m][nf], af[m], bf[nf >> 1][nf & 1], bf[nf >> 1][(nf & 1) + 2]);
        }
    }

    // ---- epilogue ----
    const size_t cbase = cHead ? ((size_t)(z >> 4) * TT * ldc + (size_t)(z & 15) * DH)
                               : (size_t)z * cZ;
    if (OUT == 0) {
        float* Cb = C + cbase + (size_t)bm * ldc + bn;
        const float* Rb = res ? res + cbase + (size_t)bm * ldc + bn : (const float*)0;
#pragma unroll
        for (int m = 0; m < MF; m++) {
            const int r0 = mrow0 + m * 16 + (lane >> 2);
#pragma unroll
            for (int h = 0; h < 2; h++) {
                const int r = r0 + h * 8;
                float* crow = Cb + (size_t)r * ldc;
                const float* rrow = Rb ? Rb + (size_t)r * ldc : (const float*)0;
#pragma unroll
                for (int nf = 0; nf < NF; nf++) {
                    const int col = ncol0 + nf * 8 + (lane & 3) * 2;
                    float2 v;
                    v.x = acc[m][nf][2*h + 0] * alpha;
                    v.y = acc[m][nf][2*h + 1] * alpha;
                    if (rrow) { v.x += rrow[col]; v.y += rrow[col + 1]; }
                    *(float2*)(crow + col) = v;
                }
            }
        }
    } else if (OUT == 2) {
        __half* Ch = Cp + cbase + (size_t)bm * ldc + bn;
#pragma unroll
        for (int m = 0; m < MF; m++) {
            const int r0 = mrow0 + m * 16 + (lane >> 2);
#pragma unroll
            for (int h = 0; h < 2; h++) {
                const int r = r0 + h * 8;
#pragma unroll
                for (int nf = 0; nf < NF; nf++) {
                    const int col = ncol0 + nf * 8 + (lane & 3) * 2;
                    __half2 hh;
                    hh.x = __float2half_rn(acc[m][nf][2*h + 0] * alpha);
                    hh.y = __float2half_rn(acc[m][nf][2*h + 1] * alpha);
                    *(__half2*)(Ch + (size_t)r * ldc + col) = hh;
                }
            }
        }
    } else {   // OUT == 3: h = sigmoid(acc) * silu(res)   (acc=gate, res=up)
        __half* Ch = Cp + cbase + (size_t)bm * ldc + bn;
        const float* Ub = res + cbase + (size_t)bm * ldc + bn;
#pragma unroll
        for (int m = 0; m < MF; m++) {
            const int r0 = mrow0 + m * 16 + (lane >> 2);
#pragma unroll
            for (int h = 0; h < 2; h++) {
                const int r = r0 + h * 8;
                const float* urow = Ub + (size_t)r * ldc;
#pragma unroll
                for (int nf = 0; nf < NF; nf++) {
                    const int col = ncol0 + nf * 8 + (lane & 3) * 2;
                    __half2 hh;
#pragma unroll
                    for (int q = 0; q < 2; q++) {
                        const float g = acc[m][nf][2*h + q];
                        const float u = urow[col + q];
                        const float sg = 1.f / (1.f + __expf(-g));
                        const float su = u / (1.f + __expf(-u));
                        ((__half*)&hh)[q] = __float2half_rn(sg * su);
                    }
                    *(__half2*)(Ch + (size_t)r * ldc + col) = hh;
                }
            }
        }
    }
}

// =====================================================================
// fp32 -> fp16 convert kernel
// =====================================================================
__global__ void __launch_bounds__(256)
half_kernel(const float* __restrict__ s, __half* __restrict__ hi, size_t n2)
{
    const float2* s2 = (const float2*)s;
    __half2* h2 = (__half2*)hi;
    for (size_t i = (size_t)blockIdx.x * 256 + threadIdx.x; i < n2; i += (size_t)gridDim.x * 256) {
        const float2 v = s2[i];
        __half2 h;
        h.x = __float2half_rn(v.x); h.y = __float2half_rn(v.y);
        h2[i] = h;
    }
}

// =====================================================================
// Family basis pool -> scores, basis, resid fp32 + resid fp16 plane
// =====================================================================
__global__ void __launch_bounds__(256)
family_kernel(const float* __restrict__ x, const float* __restrict__ fgw,
              const float* __restrict__ proto, float* __restrict__ fs_out)
{
    __shared__ float xs[D_MODEL];
    __shared__ float sc[NFAM];
    const int row = blockIdx.x;
    const int tid = threadIdx.x;
    const float* xr = x + (size_t)row * D_MODEL;
    for (int d = tid; d < D_MODEL; d += 256) xs[d] = xr[d];
    __syncthreads();

    const int warp = tid >> 5, lane = tid & 31;
    for (int f = warp; f < NFAM; f += 8) {
        const float* w = fgw + (size_t)f * D_MODEL;
        float s = 0.f;
        for (int d = lane; d < D_MODEL; d += 32) s += xs[d] * w[d];
#pragma unroll
        for (int o = 16; o; o >>= 1) s += __shfl_xor_sync(0xffffffffu, s, o);
        if (lane == 0) sc[f] = s;
    }
    __syncthreads();

    if (tid < 32) {
        float m = fmaxf(sc[tid], sc[tid + 32]);
#pragma unroll
        for (int o = 16; o; o >>= 1) m = fmaxf(m, __shfl_xor_sync(0xffffffffu, m, o));
        const float e0 = __expf(sc[tid] - m);
        const float e1 = __expf(sc[tid + 32] - m);
        float s = e0 + e1;
#pragma unroll
        for (int o = 16; o; o >>= 1) s += __shfl_xor_sync(0xffffffffu, s, o);
        const float inv = 1.f / s;
        sc[tid]      = e0 * inv;
        sc[tid + 32] = e1 * inv;
    }
    __syncthreads();

    if (tid < NFAM) fs_out[(size_t)row * NFAM + tid] = sc[tid];

    for (int d = tid; d < D_MODEL; d += 256) {
        float b = 0.f;
#pragma unroll 8
        for (int f = 0; f < NFAM; f++) b += sc[f] * proto[f * D_MODEL + d];
        const size_t idx = (size_t)row * D_MODEL + d;
        g_basis[idx] = b;
        const float r = xs[d] - b;
        g_resid[idx] = r;
        b_resid_h[idx] = __float2half_rn(r);
    }
}

// =====================================================================
// Top-16 candidates from approx fp16 coeffs, exact fp32 re-rank to top-8.
// =====================================================================
__global__ void __launch_bounds__(256)
topk_kernel(const float* __restrict__ dict_w, const float* __restrict__ enc_w,
            const float* __restrict__ bias)
{
    __shared__ float sval[256 * NCAND];
    __shared__ int   sidx[256 * NCAND];
    __shared__ float rv[256];
    __shared__ int   ri[256];
    __shared__ int   rp[256];
    __shared__ int   candi[NCAND];
    __shared__ float exv[NCAND];
    __shared__ float selv[TOPK];
    __shared__ int   seli[TOPK];

    const int row = blockIdx.x;
    const int tid = threadIdx.x;
    const __half* cr = b_coeffs + (size_t)row * DICT;

    float lv[NCAND]; int li[NCAND];
#pragma unroll
    for (int r = 0; r < NCAND; r++) { lv[r] = -FLT_MAX; li[r] = 0x7fffffff; }
    for (int j = tid; j < DICT; j += 256) {
        const float v = __half2float(cr[j]);
        if (v > lv[NCAND-1]) {
            int p = NCAND - 1;
            while (p > 0 && lv[p-1] < v) { lv[p] = lv[p-1]; li[p] = li[p-1]; p--; }
            lv[p] = v; li[p] = j;
        }
    }
#pragma unroll
    for (int r = 0; r < NCAND; r++) { sval[tid*NCAND + r] = lv[r]; sidx[tid*NCAND + r] = li[r]; }
    __syncthreads();

    for (int sel = 0; sel < NCAND; sel++) {
        float bv = -FLT_MAX; int bi = 0x7fffffff; int bp = 0;
#pragma unroll
        for (int r = 0; r < NCAND; r++) {
            const int p = tid*NCAND + r;
            const float v = sval[p]; const int ix = sidx[p];
            if (v > bv || (v == bv && ix < bi)) { bv = v; bi = ix; bp = p; }
        }
        rv[tid] = bv; ri[tid] = bi; rp[tid] = bp;
        __syncthreads();
        for (int s = 128; s > 0; s >>= 1) {
            if (tid < s) {
                if (rv[tid+s] > rv[tid] || (rv[tid+s] == rv[tid] && ri[tid+s] < ri[tid])) {
                    rv[tid] = rv[tid+s]; ri[tid] = ri[tid+s]; rp[tid] = rp[tid+s];
                }
            }
            __syncthreads();
        }
        if (tid == 0) {
            candi[sel] = ri[0];
            sval[rp[0]] = -FLT_MAX; sidx[rp[0]] = 0x7fffffff;
        }
        __syncthreads();
    }

    {
        const int warp = tid >> 5, lane = tid & 31;
        const float* rr = g_resid + (size_t)row * D_MODEL;
        for (int j = warp; j < NCAND; j += 8) {
            const float* er = enc_w + (size_t)candi[j] * D_MODEL;
            float s = 0.f;
            for (int d = lane; d < D_MODEL; d += 32) s += rr[d] * er[d];
#pragma unroll
            for (int o = 16; o; o >>= 1) s += __shfl_xor_sync(0xffffffffu, s, o);
            if (lane == 0) exv[j] = s;
        }
    }
    __syncthreads();

    if (tid == 0) {
        unsigned used = 0;
        float ssum = 0.f;
        for (int sel = 0; sel < TOPK; sel++) {
            float bv = -FLT_MAX; int bi = 0x7fffffff; int bp = -1;
            for (int j = 0; j < NCAND; j++) {
                if (used & (1u << j)) continue;
                const float v = exv[j]; const int ix = candi[j];
                if (v > bv || (v == bv && ix < bi)) { bv = v; bi = ix; bp = j; }
            }
            used |= (1u << bp);
            selv[sel] = bv; seli[sel] = bi;
            ssum += fabsf(bv);
        }
        g_spars[row] = ssum;
    }
    __syncthreads();

    for (int d = tid; d < D_MODEL; d += 256) {
        float o = g_basis[(size_t)row * D_MODEL + d] + bias[d];
#pragma unroll
        for (int j = 0; j < TOPK; j++) o += selv[j] * dict_w[(size_t)seli[j] * D_MODEL + d];
        g_xrec[(size_t)row * D_MODEL + d] = o;
    }
}

// =====================================================================
// RMSNorm -> fp16 plane
// =====================================================================
__global__ void __launch_bounds__(256)
rmsnorm_kernel(const float* __restrict__ in, const float* __restrict__ w,
               __half* __restrict__ hi, float* __restrict__ rmsbuf)
{
    __shared__ float red[256];
    const int row = blockIdx.x, tid = threadIdx.x;
    const float* xr = in + (size_t)row * D_MODEL;
    float s = 0.f;
    for (int d = tid; d < D_MODEL; d += 256) { const float v = xr[d]; s += v * v; }
    red[tid] = s;
    __syncthreads();
    for (int st = 128; st > 0; st >>= 1) { if (tid < st) red[tid] += red[tid + st]; __syncthreads(); }
    const float rms = sqrtf(red[0] / (float)D_MODEL + EPS_F);
    const float inv = 1.f / rms;
    for (int d = tid; d < D_MODEL; d += 256)
        hi[(size_t)row * D_MODEL + d] = __float2half_rn(w[d] * xr[d] * inv);
    if (tid == 0) rmsbuf[row] = rms;
}

// =====================================================================
// k_mod -> fp16 plane  [bh][t][64]   (reads fp16 k plane)
// =====================================================================
__global__ void __launch_bounds__(256)
kmod_kernel(const __half* __restrict__ kbuf, const float* __restrict__ rel)
{
    __shared__ float ks[64][65];
    __shared__ float ts[64][65];
    const int bh = blockIdx.y, b = bh >> 4, h = bh & 15;
    const int t0 = blockIdx.x * 64;
    const int tid = threadIdx.x;
    for (int i = tid; i < 4096; i += 256) {
        const int r = i >> 6, c = i & 63;
        ks[r][c] = __half2float(kbuf[(size_t)(b*TT + t0 + r) * D_MODEL + h*DH + c]);
        ts[r][c] = rel[(size_t)h*DH*DH + r*DH + c];
    }
    __syncthreads();
    const int tx = tid & 15, ty = tid >> 4;
    float acc[4][4] = {};
#pragma unroll
    for (int d = 0; d < 64; d++) {
        float ra[4], rb[4];
#pragma unroll
        for (int i = 0; i < 4; i++) ra[i] = ks[ty*4 + i][d];
#pragma unroll
        for (int j = 0; j < 4; j++) rb[j] = ts[d][tx*4 + j];
#pragma unroll
        for (int i = 0; i < 4; i++)
#pragma unroll
            for (int j = 0; j < 4; j++) acc[i][j] += ra[i] * rb[j];
    }
#pragma unroll
    for (int i = 0; i < 4; i++)
#pragma unroll
        for (int j = 0; j < 4; j++)
            b_kmod[((size_t)bh*TT + t0 + ty*4 + i) * DH + tx*4 + j] = __float2half_rn(acc[i][j]);
}

// =====================================================================
// V transpose -> fp16 plane  [bh][64][t]   (reads fp16 v plane)
// =====================================================================
__global__ void __launch_bounds__(256)
vtrans_kernel(const __half* __restrict__ v)
{
    __shared__ __half t[64][72];
    const int z = blockIdx.y, b = z >> 4, h = z & 15;
    const int t0 = blockIdx.x * 64;
    for (int i = threadIdx.x; i < 4096; i += 256) {
        const int r = i >> 6, c = i & 63;
        t[r][c] = v[(size_t)(b*TT + t0 + r) * D_MODEL + h*DH + c];
    }
    __syncthreads();
    for (int i = threadIdx.x; i < 4096; i += 256) {
        const int e = i >> 6, r = i & 63;
        b_vt[(size_t)z * DH * TT + (size_t)e * TT + t0 + r] = t[r][e];
    }
}

// =====================================================================
// Row softmax over 2048: reads fp16 logits, writes fp32 probs to d_out
// and fp16 probs in place over the logits plane.
// =====================================================================
__global__ void __launch_bounds__(256)
softmax_kernel(const __half* __restrict__ L, float* __restrict__ P,
               __half* __restrict__ ph)
{
    __shared__ float red[256];
    const size_t row = blockIdx.x;
    const __half* lr = L + row * (size_t)TT;
    float* p = P + row * (size_t)TT;
    __half* oh = ph + row * (size_t)TT;
    const int tid = threadIdx.x;
    float v[8];
#pragma unroll
    for (int i = 0; i < 8; i++) v[i] = __half2float(lr[tid + i*256]);
    float m = v[0];
#pragma unroll
    for (int i = 1; i < 8; i++) m = fmaxf(m, v[i]);
    red[tid] = m;
    __syncthreads();
    for (int st = 128; st > 0; st >>= 1) { if (tid < st) red[tid] = fmaxf(red[tid], red[tid+st]); __syncthreads(); }
    m = red[0];
    __syncthreads();
    float s = 0.f;
#pragma unroll
    for (int i = 0; i < 8; i++) { v[i] = __expf(v[i] - m); s += v[i]; }
    red[tid] = s;
    __syncthreads();
    for (int st = 128; st > 0; st >>= 1) { if (tid < st) red[tid] += red[tid+st]; __syncthreads(); }
    const float inv = 1.f / red[0];
#pragma unroll
    for (int i = 0; i < 8; i++) {
        const float vv = v[i] * inv;
        p[tid + i*256] = vv;
        oh[tid + i*256] = __float2half_rn(vv);
    }
}

// =====================================================================
// Final scalars
// =====================================================================
__global__ void __launch_bounds__(256)
finalize_kernel(float* __restrict__ out)
{
    __shared__ float s1[256], s2[256], s3[256];
    const int tid = threadIdx.x;
    float a = 0.f, b = 0.f, c = 0.f;
    for (int i = tid; i < BT; i += 256) { a += g_spars[i]; b += g_rms1[i]; c += g_rms2[i]; }
    s1[tid] = a; s2[tid] = b; s3[tid] = c;
    __syncthreads();
    for (int st = 128; st > 0; st >>= 1) {
        if (tid < st) { s1[tid] += s1[tid+st]; s2[tid] += s2[tid+st]; s3[tid] += s3[tid+st]; }
        __syncthreads();
    }
    if (tid == 0) {
        out[SC_OFF + 0] = s1[0] / ((float)BB * (float)TT * (float)DICT);
        out[SC_OFF + 1] = s2[0] / (float)BT;
        out[SC_OFF + 2] = s3[0] / (float)BT;
    }
}

// =====================================================================
// host launcher
// =====================================================================
extern "C" void kernel_launch(void* const* d_in, const int* in_sizes, int n_in,
                              void* d_out, int out_size)
{
    (void)in_sizes; (void)n_in; (void)out_size;
    const float* x     = (const float*)d_in[0];
    const float* proto = (const float*)d_in[2];
    const float* fgw   = (const float*)d_in[3];
    const float* dictw = (const float*)d_in[4];
    const float* encw  = (const float*)d_in[5];
    const float* wq    = (const float*)d_in[6];
    const float* wk    = (const float*)d_in[7];
    const float* wv    = (const float*)d_in[8];
    const float* wo    = (const float*)d_in[9];
    const float* rel   = (const float*)d_in[10];
    const float* gatew = (const float*)d_in[11];
    const float* upw   = (const float*)d_in[12];
    const float* downw = (const float*)d_in[13];
    const float* n1w   = (const float*)d_in[14];
    const float* n2w   = (const float*)d_in[15];
    const float* bias  = (const float*)d_in[16];
    float* out = (float*)d_out;

    const int SM_128 = 3 * (16384 + 16384);   // 98304
    const int SM_64  = 3 * (16384 +  8192);   // 73728
    cudaFuncSetAttribute(mma_gemm<128,0>, cudaFuncAttributeMaxDynamicSharedMemorySize, SM_128);
    cudaFuncSetAttribute(mma_gemm<128,2>, cudaFuncAttributeMaxDynamicSharedMemorySize, SM_128);
    cudaFuncSetAttribute(mma_gemm<128,3>, cudaFuncAttributeMaxDynamicSharedMemorySize, SM_128);
    cudaFuncSetAttribute(mma_gemm<64,2>,  cudaFuncAttributeMaxDynamicSharedMemorySize, SM_64);

    float *p_xrec, *p_x2, *p_up, *p_rms1, *p_rms2;
    cudaGetSymbolAddress((void**)&p_xrec, g_xrec);
    cudaGetSymbolAddress((void**)&p_x2,   g_x2);
    cudaGetSymbolAddress((void**)&p_up,   g_up);
    cudaGetSymbolAddress((void**)&p_rms1, g_rms1);
    cudaGetSymbolAddress((void**)&p_rms2, g_rms2);

    __half *pb_coeffs, *pb_resid, *pb_enc, *pb_normed, *pb_normed2, *pb_qkv, *pb_kmod,
           *pb_vt, *pb_ctx, *pb_h, *pb_attn, *pb_wqkv, *pb_wo, *pb_gw, *pb_uw, *pb_dw;
    cudaGetSymbolAddress((void**)&pb_coeffs,  b_coeffs);
    cudaGetSymbolAddress((void**)&pb_resid,   b_resid_h);
    cudaGetSymbolAddress((void**)&pb_enc,     b_enc_h);
    cudaGetSymbolAddress((void**)&pb_normed,  b_normed);
    cudaGetSymbolAddress((void**)&pb_normed2, b_normed2);
    cudaGetSymbolAddress((void**)&pb_qkv,     b_qkv);
    cudaGetSymbolAddress((void**)&pb_kmod,    b_kmod);
    cudaGetSymbolAddress((void**)&pb_vt,      b_vt);
    cudaGetSymbolAddress((void**)&pb_ctx,     b_ctx);
    cudaGetSymbolAddress((void**)&pb_h,       b_h);
    cudaGetSymbolAddress((void**)&pb_attn,    b_attn);
    cudaGetSymbolAddress((void**)&pb_wqkv,    b_wqkv);
    cudaGetSymbolAddress((void**)&pb_wo,      b_wo);
    cudaGetSymbolAddress((void**)&pb_gw,      b_gw);
    cudaGetSymbolAddress((void**)&pb_uw,      b_uw);
    cudaGetSymbolAddress((void**)&pb_dw,      b_dw);

    // weight converts
    half_kernel<<<1024, 256>>>(encw, pb_enc, PE/2);
    half_kernel<<<256, 256>>>(wq, pb_wqkv,          PW/2);
    half_kernel<<<256, 256>>>(wk, pb_wqkv + PW,     PW/2);
    half_kernel<<<256, 256>>>(wv, pb_wqkv + 2*PW,   PW/2);
    family_kernel<<<BT, 256>>>(x, fgw, proto, out + FS_OFF);

    // approx coeffs (fp16 out; exact re-rank in topk)
    mma_gemm<128,2><<<dim3(DICT/128, BT/128, 1), 256, SM_128>>>(
        pb_resid, D_MODEL, 0, 0, pb_enc, D_MODEL, 0,
        nullptr, DICT, 0, 0, pb_coeffs, nullptr, D_MODEL, 1.0f);

    // remaining weight converts (overlap with coeffs GEMM tail)
    half_kernel<<<256, 256>>>(wo,    pb_wo, PW/2);
    half_kernel<<<512, 256>>>(gatew, pb_gw, PF/2);
    half_kernel<<<512, 256>>>(upw,   pb_uw, PF/2);
    half_kernel<<<512, 256>>>(downw, pb_dw, PF/2);

    // top-16 + exact fp32 re-rank -> x_rec, sparsity
    topk_kernel<<<BT, 256>>>(dictw, encw, bias);

    // norm1 -> fp16 plane
    rmsnorm_kernel<<<BT, 256>>>(p_xrec, n1w, pb_normed, p_rms1);

    // q,k,v in ONE batched launch (fp16 planes out)
    mma_gemm<128,2><<<dim3(D_MODEL/128, BT/128, 3), 256, SM_128>>>(
        pb_normed, D_MODEL, 0, 0, pb_wqkv, D_MODEL, PW,
        nullptr, D_MODEL, PD, 0, pb_qkv, nullptr, D_MODEL, 1.0f);

    // k_mod + V transpose (fp16 in/out)
    kmod_kernel<<<dim3(TT/64, BB*N_HEADS), 256>>>(pb_qkv + PD, rel);
    vtrans_kernel<<<dim3(TT/64, BB*N_HEADS), 256>>>(pb_qkv + 2*PD);

    // logits -> fp16 plane (alpha fused), softmax -> fp32 d_out + fp16 in place
    mma_gemm<128,2><<<dim3(TT/128, TT/128, BB*N_HEADS), 256, SM_128>>>(
        pb_qkv, D_MODEL, 0, 1, pb_kmod, DH, (size_t)TT*DH,
        nullptr, TT, (size_t)TT*TT, 0, pb_attn, nullptr, DH, 0.125f);
    softmax_kernel<<<BB*N_HEADS*TT, 256>>>(pb_attn, out + ATT_OFF, pb_attn);

    // ctx = attn @ v (fp16 out, head-sliced)
    mma_gemm<64,2><<<dim3(1, TT/128, BB*N_HEADS), 256, SM_64>>>(
        pb_attn, TT, (size_t)TT*TT, 0, pb_vt, TT, (size_t)DH*TT,
        nullptr, D_MODEL, 0, 1, pb_ctx, nullptr, TT, 1.0f);

    // x2 = x + ctx @ wo^T
    mma_gemm<128,0><<<dim3(D_MODEL/128, BT/128, 1), 256, SM_128>>>(
        pb_ctx, D_MODEL, 0, 0, pb_wo, D_MODEL, 0,
        p_x2, D_MODEL, 0, 0, nullptr, x, D_MODEL, 1.0f);

    // norm2 -> fp16 plane
    rmsnorm_kernel<<<BT, 256>>>(p_x2, n2w, pb_normed2, p_rms2);

    // FFN: up (fp32), gate (+fused activation -> b_h fp16)
    mma_gemm<128,0><<<dim3(D_FF/128, BT/128, 1), 256, SM_128>>>(
        pb_normed2, D_MODEL, 0, 0, pb_uw, D_MODEL, 0,
        p_up, D_FF, 0, 0, nullptr, nullptr, D_MODEL, 1.0f);
    mma_gemm<128,3><<<dim3(D_FF/128, BT/128, 1), 256, SM_128>>>(
        pb_normed2, D_MODEL, 0, 0, pb_gw, D_MODEL, 0,
        nullptr, D_FF, 0, 0, pb_h, p_up, D_MODEL, 1.0f);

    // final x = x2 + h @ down^T -> d_out
    mma_gemm<128,0><<<dim3(D_MODEL/128, BT/128, 1), 256, SM_128>>>(
        pb_h, D_FF, 0, 0, pb_dw, D_FF, 0,
        out + X_OFF, D_MODEL, 0, 0, nullptr, p_x2, D_FF, 1.0f);

    // scalars
    finalize_kernel<<<1, 256>>>(out);
}